// round 1
// baseline (speedup 1.0000x reference)
#include <cuda_runtime.h>
#include <cuda_bf16.h>

// HashGrid: multiresolution hash encoding (instant-NGP / tcnn style)
// x: [N, 2] float32 in [0,1); table: [16, 524288, 2] float32
// out: [N, 32] float32 (16 levels x 2 features, concatenated)

#define NPTS      2097152
#define NLEV      16
#define TSIZE     524288u
#define TMASK     0x7FFFFu
#define PRIME_Y   2654435761u

__global__ __launch_bounds__(256) void hashgrid_kernel(
    const float2* __restrict__ x,
    const float*  __restrict__ table,
    float*        __restrict__ out,
    int n)
{
    int i = blockIdx.x * blockDim.x + threadIdx.x;
    if (i >= n) return;

    const float2 p = x[i];

    // scale = 16*1.5^l - 1 (exact in double, correctly rounded to float)
    // res   = ceil(scale) + 1
    // dense (res*res <= T) for l < 10, spatial hash for l >= 10
    const float scales[NLEV] = {
        15.0f, 23.0f, 35.0f, 53.0f, 80.0f, 120.5f, 181.25f, 272.375f,
        409.0625f, 614.09375f, 921.640625f, 1382.9609375f,
        2074.94140625f, 3112.912109375f, 4669.8681640625f, 7005.30224609375f
    };
    const unsigned resv[NLEV] = {
        16u, 24u, 36u, 54u, 81u, 122u, 183u, 274u,
        411u, 616u, 923u, 1384u, 2076u, 3114u, 4671u, 7007u
    };

    float4 buf;
    float4* out4 = reinterpret_cast<float4*>(out);

#pragma unroll
    for (int l = 0; l < NLEV; ++l) {
        const float2* __restrict__ tab =
            reinterpret_cast<const float2*>(table) + (size_t)l * TSIZE;

        // pos = x*scale + 0.5 (separate mul/add like the reference)
        float px = __fadd_rn(__fmul_rn(p.x, scales[l]), 0.5f);
        float py = __fadd_rn(__fmul_rn(p.y, scales[l]), 0.5f);
        float fx = floorf(px), fy = floorf(py);
        float tx = px - fx,    ty = py - fy;   // interpolation fracs
        unsigned gx = (unsigned)fx, gy = (unsigned)fy;

        unsigned i00, i10, i01, i11;
        if (l < 10) {
            // dense grid: idx = (cx + cy*res) % T
            unsigned r    = resv[l];
            unsigned row0 = gy * r;
            unsigned row1 = row0 + r;
            i00 = (gx     + row0) & TMASK;
            i10 = (gx + 1 + row0) & TMASK;
            i01 = (gx     + row1) & TMASK;
            i11 = (gx + 1 + row1) & TMASK;
        } else {
            // spatial hash: idx = (cx ^ (cy*PRIME)) % T
            unsigned hy0 = gy * PRIME_Y;
            unsigned hy1 = hy0 + PRIME_Y;   // (gy+1)*PRIME
            i00 = ( gx      ^ hy0) & TMASK;
            i10 = ((gx + 1) ^ hy0) & TMASK;
            i01 = ( gx      ^ hy1) & TMASK;
            i11 = ((gx + 1) ^ hy1) & TMASK;
        }

        float2 v00 = __ldg(tab + i00);
        float2 v10 = __ldg(tab + i10);
        float2 v01 = __ldg(tab + i01);
        float2 v11 = __ldg(tab + i11);

        float wx0 = 1.0f - tx, wy0 = 1.0f - ty;
        float w00 = wx0 * wy0;
        float w01 = wx0 * ty;
        float w10 = tx  * wy0;
        float w11 = tx  * ty;

        // reference accumulation order: (0,0), (0,1), (1,0), (1,1)
        float f0 = v00.x * w00 + v01.x * w01 + v10.x * w10 + v11.x * w11;
        float f1 = v00.y * w00 + v01.y * w01 + v10.y * w10 + v11.y * w11;

        if (l & 1) {
            buf.z = f0; buf.w = f1;
            out4[(size_t)i * 8 + (l >> 1)] = buf;   // packed 16B store
        } else {
            buf.x = f0; buf.y = f1;
        }
    }
}

extern "C" void kernel_launch(void* const* d_in, const int* in_sizes, int n_in,
                              void* d_out, int out_size)
{
    const float2* x     = (const float2*)d_in[0];   // [N,2] float32
    const float*  table = (const float*) d_in[1];   // [16, 524288, 2] float32
    float*        out   = (float*)d_out;            // [N,32] float32

    int n = in_sizes[0] / 2;                        // number of points
    int threads = 256;
    int blocks  = (n + threads - 1) / threads;
    hashgrid_kernel<<<blocks, threads>>>(x, table, out, n);
}

// round 6
// speedup vs baseline: 1.8450x; 1.8450x over previous
#include <cuda_runtime.h>
#include <cuda_bf16.h>

// HashGrid multiresolution hash encoding.
// x: [N,2] f32, table: [16, 524288, 2] f32, out: [N,32] f32.
// L1-wavefront-bound kernel: minimize gather requests & lines/request.
//  - levels 0-4: staged in shared memory (compact res^2+res+1 regions, 92.4KB)
//  - levels 5-9 (dense): i10=i00+1 -> fuse both corners into one aligned LDG.128
//    when i00 even (table reinterpreted as float4 pair array, no repack)
//  - levels 10-15 (hashed): i10=i00^1 when gx even -> same float4 pair

#define NLEV     16
#define TSIZE    524288u
#define TMASK    0x7FFFFu
#define PRIME_Y  2654435761u
#define THREADS  512
#define NBLOCKS  296   // 2 per SM x 148 SMs, persistent

// levels 0-4 staged region sizes: res^2 + res + 1
#define C0 273
#define C1 601
#define C2 1333
#define C3 2971
#define C4 6643
#define SM_ENTRIES (C0 + C1 + C2 + C3 + C4)   // 11821 float2 = 94568 B

__global__ __launch_bounds__(THREADS, 2) void hashgrid_kernel(
    const float2* __restrict__ x,
    const float*  __restrict__ table,
    float*        __restrict__ out,
    int n)
{
    extern __shared__ float2 stab[];

    // ---- stage levels 0-4 into smem (coalesced fill, amortized: persistent grid)
    {
        const int cnt[5] = {C0, C1, C2, C3, C4};
        const int off[5] = {0, C0, C0 + C1, C0 + C1 + C2, C0 + C1 + C2 + C3};
#pragma unroll
        for (int l = 0; l < 5; ++l) {
            const float2* src = reinterpret_cast<const float2*>(table) + (size_t)l * TSIZE;
            float2* dst = stab + off[l];
            for (int e = threadIdx.x; e < cnt[l]; e += THREADS)
                dst[e] = src[e];
        }
    }
    __syncthreads();

    // scale = 16*1.5^l - 1 (exact), res = ceil(scale)+1. dense for l<10.
    const float scales[NLEV] = {
        15.0f, 23.0f, 35.0f, 53.0f, 80.0f, 120.5f, 181.25f, 272.375f,
        409.0625f, 614.09375f, 921.640625f, 1382.9609375f,
        2074.94140625f, 3112.912109375f, 4669.8681640625f, 7005.30224609375f
    };
    const unsigned resv[NLEV] = {
        16u, 24u, 36u, 54u, 81u, 122u, 183u, 274u,
        411u, 616u, 923u, 1384u, 2076u, 3114u, 4671u, 7007u
    };
    const int smoff[5] = {0, C0, C0 + C1, C0 + C1 + C2, C0 + C1 + C2 + C3};

    const float4* __restrict__ tab4 = reinterpret_cast<const float4*>(table);

    for (int i = blockIdx.x * THREADS + threadIdx.x; i < n; i += NBLOCKS * THREADS) {
        const float2 p = x[i];
        float4* out4 = reinterpret_cast<float4*>(out) + (size_t)i * 8;
        float4 buf;

#pragma unroll
        for (int l = 0; l < NLEV; ++l) {
            float px = p.x * scales[l] + 0.5f;
            float py = p.y * scales[l] + 0.5f;
            float fx = floorf(px), fy = floorf(py);
            float tx = px - fx,    ty = py - fy;
            unsigned gx = (unsigned)fx, gy = (unsigned)fy;

            float2 v00, v10, v01, v11;

            if (l < 5) {
                // shared-memory dense lookup
                const float2* st = stab + smoff[l];
                unsigned b0 = gx + gy * resv[l];
                unsigned b1 = b0 + resv[l];
                v00 = st[b0];     v10 = st[b0 + 1];
                v01 = st[b1];     v11 = st[b1 + 1];
            } else if (l < 10) {
                // global dense: i10 = i00+1 (never wraps: res^2+res < T)
                const float4* t4 = tab4 + (size_t)l * (TSIZE / 2);
                unsigned b0 = gx + gy * resv[l];
                unsigned b1 = b0 + resv[l];
                if (!(b0 & 1)) {
                    float4 q = __ldg(t4 + (b0 >> 1));
                    v00 = make_float2(q.x, q.y); v10 = make_float2(q.z, q.w);
                } else {
                    float4 qa = __ldg(t4 + (b0 >> 1));
                    float4 qb = __ldg(t4 + (b0 >> 1) + 1);
                    v00 = make_float2(qa.z, qa.w); v10 = make_float2(qb.x, qb.y);
                }
                if (!(b1 & 1)) {
                    float4 q = __ldg(t4 + (b1 >> 1));
                    v01 = make_float2(q.x, q.y); v11 = make_float2(q.z, q.w);
                } else {
                    float4 qa = __ldg(t4 + (b1 >> 1));
                    float4 qb = __ldg(t4 + (b1 >> 1) + 1);
                    v01 = make_float2(qa.z, qa.w); v11 = make_float2(qb.x, qb.y);
                }
            } else {
                // global hashed: idx = (cx ^ cy*PRIME) & TMASK
                const float4* t4 = tab4 + (size_t)l * (TSIZE / 2);
                unsigned hy0 = gy * PRIME_Y;
                unsigned hy1 = hy0 + PRIME_Y;
                unsigned i00 = (gx ^ hy0) & TMASK;
                unsigned i01 = (gx ^ hy1) & TMASK;
                if (!(gx & 1)) {
                    // gx even: i10 = i00^1, i11 = i01^1 -> one pair load per row
                    float4 q0 = __ldg(t4 + (i00 >> 1));
                    float4 q1 = __ldg(t4 + (i01 >> 1));
                    float2 q0l = make_float2(q0.x, q0.y), q0h = make_float2(q0.z, q0.w);
                    float2 q1l = make_float2(q1.x, q1.y), q1h = make_float2(q1.z, q1.w);
                    if (i00 & 1) { v00 = q0h; v10 = q0l; } else { v00 = q0l; v10 = q0h; }
                    if (i01 & 1) { v01 = q1h; v11 = q1l; } else { v01 = q1l; v11 = q1h; }
                } else {
                    unsigned i10 = ((gx + 1) ^ hy0) & TMASK;
                    unsigned i11 = ((gx + 1) ^ hy1) & TMASK;
                    float4 qa = __ldg(t4 + (i00 >> 1));
                    float4 qb = __ldg(t4 + (i10 >> 1));
                    float4 qc = __ldg(t4 + (i01 >> 1));
                    float4 qd = __ldg(t4 + (i11 >> 1));
                    v00 = (i00 & 1) ? make_float2(qa.z, qa.w) : make_float2(qa.x, qa.y);
                    v10 = (i10 & 1) ? make_float2(qb.z, qb.w) : make_float2(qb.x, qb.y);
                    v01 = (i01 & 1) ? make_float2(qc.z, qc.w) : make_float2(qc.x, qc.y);
                    v11 = (i11 & 1) ? make_float2(qd.z, qd.w) : make_float2(qd.x, qd.y);
                }
            }

            float wx0 = 1.0f - tx, wy0 = 1.0f - ty;
            float w00 = wx0 * wy0;
            float w01 = wx0 * ty;
            float w10 = tx  * wy0;
            float w11 = tx  * ty;

            float f0 = v00.x * w00 + v01.x * w01 + v10.x * w10 + v11.x * w11;
            float f1 = v00.y * w00 + v01.y * w01 + v10.y * w10 + v11.y * w11;

            if (l & 1) {
                buf.z = f0; buf.w = f1;
                out4[l >> 1] = buf;
            } else {
                buf.x = f0; buf.y = f1;
            }
        }
    }
}

extern "C" void kernel_launch(void* const* d_in, const int* in_sizes, int n_in,
                              void* d_out, int out_size)
{
    const float2* x     = (const float2*)d_in[0];
    const float*  table = (const float*) d_in[1];
    float*        out   = (float*)d_out;

    int n = in_sizes[0] / 2;
    const int smem_bytes = SM_ENTRIES * sizeof(float2);   // 94568 B
    // idempotent; required for >48KB dynamic smem (safe during graph capture)
    cudaFuncSetAttribute(hashgrid_kernel,
                         cudaFuncAttributeMaxDynamicSharedMemorySize, smem_bytes);
    hashgrid_kernel<<<NBLOCKS, THREADS, smem_bytes>>>(x, table, out, n);
}